// round 1
// baseline (speedup 1.0000x reference)
#include <cuda_runtime.h>
#include <math.h>

// ---------------------------------------------------------------------------
// GroupedQueryAttentionWithoutRoPE
//   B=2, S=1024, D=2048, 32 heads in 8 groups of 4, HD=64, causal + pad mask.
//   Pipeline: q = Q@w_q^T ; k = K@w_k^T ; v = V@w_v^T ; flash-attn ; out@w_o^T+b.
//   Round 0: all-fp32 SIMT baseline (tiled GEMM + online-softmax attention).
// ---------------------------------------------------------------------------

#define D_MODEL   2048
#define N_GROUPS  8
#define HEAD_DIM  64
#define HGROUP    4                  // heads per group
#define BATCH     2
#define SEQ       1024
#define M_ROWS    (BATCH * SEQ)      // 2048
#define KV_DIM    (N_GROUPS * HEAD_DIM) // 512

// Scratch (allocation-free rule: __device__ globals)
__device__ float g_q  [M_ROWS * D_MODEL];   // 16 MB
__device__ float g_k  [M_ROWS * KV_DIM];    // 4 MB
__device__ float g_v  [M_ROWS * KV_DIM];    // 4 MB
__device__ float g_att[M_ROWS * D_MODEL];   // 16 MB

// ---------------------------------------------------------------------------
// GEMM: C[M][N] = A[M][K] * W[N][K]^T (+ bias[N])
// BM=BN=128, BK=8, 256 threads, 8x8 micro-tile per thread.
// ---------------------------------------------------------------------------
__global__ __launch_bounds__(256) void gemm_nt_kernel(
    const float* __restrict__ A, const float* __restrict__ W,
    const float* __restrict__ bias, float* __restrict__ C,
    int M, int N, int K)
{
    const int BM = 128, BN = 128, BK = 8;
    __shared__ float As[BK][BM + 4];   // [k][m], padded rows (132 floats)
    __shared__ float Bs[BK][BN + 4];   // [k][n]

    const int bm = blockIdx.y * BM;
    const int bn = blockIdx.x * BN;
    const int tid = threadIdx.x;
    const int tm = tid >> 4;           // 0..15
    const int tn = tid & 15;           // 0..15

    float acc[8][8];
#pragma unroll
    for (int i = 0; i < 8; i++)
#pragma unroll
        for (int j = 0; j < 8; j++) acc[i][j] = 0.f;

    // loader mapping: 2 threads per row, float4 each -> BK=8 columns
    const int lr = tid >> 1;            // 0..127
    const int lk = (tid & 1) << 2;      // 0 or 4
    const float* Ap = A + (size_t)(bm + lr) * K + lk;
    const float* Wp = W + (size_t)(bn + lr) * K + lk;

    for (int k0 = 0; k0 < K; k0 += BK) {
        float4 a4 = *(const float4*)(Ap + k0);
        float4 b4 = *(const float4*)(Wp + k0);
        As[lk + 0][lr] = a4.x; As[lk + 1][lr] = a4.y;
        As[lk + 2][lr] = a4.z; As[lk + 3][lr] = a4.w;
        Bs[lk + 0][lr] = b4.x; Bs[lk + 1][lr] = b4.y;
        Bs[lk + 2][lr] = b4.z; Bs[lk + 3][lr] = b4.w;
        __syncthreads();

#pragma unroll
        for (int kk = 0; kk < BK; kk++) {
            float a[8], b[8];
#pragma unroll
            for (int i = 0; i < 8; i++) a[i] = As[kk][tm * 8 + i];
#pragma unroll
            for (int j = 0; j < 8; j++) b[j] = Bs[kk][tn * 8 + j];
#pragma unroll
            for (int i = 0; i < 8; i++)
#pragma unroll
                for (int j = 0; j < 8; j++)
                    acc[i][j] = fmaf(a[i], b[j], acc[i][j]);
        }
        __syncthreads();
    }

#pragma unroll
    for (int i = 0; i < 8; i++) {
        const int row = bm + tm * 8 + i;
        float* Crow = C + (size_t)row * N + bn + tn * 8;
#pragma unroll
        for (int j = 0; j < 8; j++) {
            float v = acc[i][j];
            if (bias) v += bias[bn + tn * 8 + j];
            Crow[j] = v;
        }
    }
}

// ---------------------------------------------------------------------------
// Flash-attention (fp32, causal + pad mask, online softmax).
// grid: (SEQ/BQ, BATCH*N_GROUPS*HGROUP) = (8, 64); block = 128 threads.
// Each thread owns one query row: q in 64 regs, acc in 64 regs.
// K/V tiles (64x64) staged in smem (smem reused from Q staging).
// ---------------------------------------------------------------------------
#define BQ  128
#define BKV 64

__global__ __launch_bounds__(128) void attn_kernel(const int* __restrict__ amask,
                                                   float* __restrict__ out)
{
    __shared__ float smem[BQ * 65];     // 8320 floats = 2 * (64*65): reused
    __shared__ int   msk[BKV];

    const int t  = threadIdx.x;         // query row within tile
    const int qb = blockIdx.x;
    const int h  = blockIdx.y;          // b*32 + g*4 + hg
    const int hg = h & 3;
    const int g  = (h >> 2) & 7;
    const int b  = h >> 5;
    const int sq = qb * BQ + t;

    // ---- stage Q tile [BQ][64] coalesced, then move own row to registers
    {
        const float* qbase = g_q + (size_t)(b * SEQ + qb * BQ) * D_MODEL
                           + g * (HGROUP * HEAD_DIM) + hg * HEAD_DIM;
#pragma unroll
        for (int i = 0; i < 16; i++) {
            int idx = t + i * 128;            // 0..2047 float4 slots
            int r   = idx >> 4;               // 0..127
            int c4  = (idx & 15) << 2;        // 0..60
            float4 v4 = *(const float4*)(qbase + (size_t)r * D_MODEL + c4);
            smem[r * 65 + c4 + 0] = v4.x;
            smem[r * 65 + c4 + 1] = v4.y;
            smem[r * 65 + c4 + 2] = v4.z;
            smem[r * 65 + c4 + 3] = v4.w;
        }
    }
    __syncthreads();
    float qr[64];
#pragma unroll
    for (int d = 0; d < 64; d++) qr[d] = smem[t * 65 + d];
    __syncthreads();

    float* Ks = smem;
    float* Vs = smem + BKV * 65;

    float acc[64];
#pragma unroll
    for (int d = 0; d < 64; d++) acc[d] = 0.f;
    float mrun = -INFINITY;
    float lrun = 0.f;

    const int nkb = (qb * BQ + BQ - 1) / BKV + 1;   // causal tile limit
    for (int kb = 0; kb < nkb; kb++) {
        const float* kbase = g_k + (size_t)(b * SEQ + kb * BKV) * KV_DIM + g * HEAD_DIM;
        const float* vbase = g_v + (size_t)(b * SEQ + kb * BKV) * KV_DIM + g * HEAD_DIM;
#pragma unroll
        for (int i = 0; i < 8; i++) {
            int idx = t + i * 128;            // 0..1023 float4 slots
            int r   = idx >> 4;               // 0..63
            int c4  = (idx & 15) << 2;
            float4 k4 = *(const float4*)(kbase + (size_t)r * KV_DIM + c4);
            Ks[r * 65 + c4 + 0] = k4.x; Ks[r * 65 + c4 + 1] = k4.y;
            Ks[r * 65 + c4 + 2] = k4.z; Ks[r * 65 + c4 + 3] = k4.w;
            float4 v4 = *(const float4*)(vbase + (size_t)r * KV_DIM + c4);
            Vs[r * 65 + c4 + 0] = v4.x; Vs[r * 65 + c4 + 1] = v4.y;
            Vs[r * 65 + c4 + 2] = v4.z; Vs[r * 65 + c4 + 3] = v4.w;
        }
        if (t < BKV) msk[t] = amask[b * SEQ + kb * BKV + t];
        __syncthreads();

        int jend = sq - kb * BKV + 1;         // causal: key index <= sq
        if (jend > BKV) jend = BKV;
        for (int j = 0; j < jend; j++) {
            if (msk[j] == 0) continue;        // padding mask -> -inf -> p=0
            float s = 0.f;
#pragma unroll
            for (int d = 0; d < 64; d++) s = fmaf(qr[d], Ks[j * 65 + d], s);
            s *= 0.125f;                      // 1/sqrt(64)
            if (s > mrun) {
                float corr = __expf(mrun - s);   // first hit: exp(-inf)=0
                lrun = lrun * corr + 1.f;
#pragma unroll
                for (int d = 0; d < 64; d++)
                    acc[d] = fmaf(acc[d], corr, Vs[j * 65 + d]);
                mrun = s;
            } else {
                float p = __expf(s - mrun);
                lrun += p;
#pragma unroll
                for (int d = 0; d < 64; d++)
                    acc[d] = fmaf(p, Vs[j * 65 + d], acc[d]);
            }
        }
        __syncthreads();
    }

    const float inv = 1.f / lrun;
    float* obase = out + (size_t)(b * SEQ + sq) * D_MODEL
                 + g * (HGROUP * HEAD_DIM) + hg * HEAD_DIM;
#pragma unroll
    for (int d4 = 0; d4 < 64; d4 += 4) {
        float4 o4 = make_float4(acc[d4 + 0] * inv, acc[d4 + 1] * inv,
                                acc[d4 + 2] * inv, acc[d4 + 3] * inv);
        *(float4*)(obase + d4) = o4;
    }
}

// ---------------------------------------------------------------------------
// Launch: 5 kernels in stream order (graph-capturable, allocation-free).
// ---------------------------------------------------------------------------
extern "C" void kernel_launch(void* const* d_in, const int* in_sizes, int n_in,
                              void* d_out, int out_size)
{
    const float* Q     = (const float*)d_in[0];
    const float* K     = (const float*)d_in[1];
    const float* V     = (const float*)d_in[2];
    const int*   amask = (const int*)  d_in[3];
    const float* w_q   = (const float*)d_in[4];
    const float* w_k   = (const float*)d_in[5];
    const float* w_v   = (const float*)d_in[6];
    const float* w_o   = (const float*)d_in[7];
    const float* b_o   = (const float*)d_in[8];
    float* out = (float*)d_out;

    float *pq, *pk, *pv, *patt;
    cudaGetSymbolAddress((void**)&pq,   g_q);
    cudaGetSymbolAddress((void**)&pk,   g_k);
    cudaGetSymbolAddress((void**)&pv,   g_v);
    cudaGetSymbolAddress((void**)&patt, g_att);

    dim3 blk(256);
    // q = Q @ w_q^T : [2048 x 2048] * [2048 x 2048]^T
    gemm_nt_kernel<<<dim3(D_MODEL / 128, M_ROWS / 128), blk>>>(
        Q, w_q, nullptr, pq, M_ROWS, D_MODEL, D_MODEL);
    // k = K @ w_k^T : [2048 x 2048] * [512 x 2048]^T
    gemm_nt_kernel<<<dim3(KV_DIM / 128, M_ROWS / 128), blk>>>(
        K, w_k, nullptr, pk, M_ROWS, KV_DIM, D_MODEL);
    // v = V @ w_v^T
    gemm_nt_kernel<<<dim3(KV_DIM / 128, M_ROWS / 128), blk>>>(
        V, w_v, nullptr, pv, M_ROWS, KV_DIM, D_MODEL);
    // attention -> g_att
    attn_kernel<<<dim3(SEQ / BQ, BATCH * N_GROUPS * HGROUP), dim3(128)>>>(amask, patt);
    // out = att @ w_o^T + b_o
    gemm_nt_kernel<<<dim3(D_MODEL / 128, M_ROWS / 128), blk>>>(
        patt, w_o, b_o, out, M_ROWS, D_MODEL, D_MODEL);
}

// round 2
// speedup vs baseline: 2.0990x; 2.0990x over previous
#include <cuda_runtime.h>
#include <math.h>
#include <stdint.h>

// ---------------------------------------------------------------------------
// GroupedQueryAttentionWithoutRoPE — Round 2
//   GEMMs: tf32 mma.sync.m16n8k8 (tensor cores), BM=BN=128, BK=16.
//   Attention: fp32 SIMT flash, float4 smem loads (stride 68).
// ---------------------------------------------------------------------------

#define D_MODEL   2048
#define N_GROUPS  8
#define HEAD_DIM  64
#define HGROUP    4
#define BATCH     2
#define SEQ       1024
#define M_ROWS    (BATCH * SEQ)          // 2048
#define KV_DIM    (N_GROUPS * HEAD_DIM)  // 512

__device__ float g_q  [M_ROWS * D_MODEL];
__device__ float g_k  [M_ROWS * KV_DIM];
__device__ float g_v  [M_ROWS * KV_DIM];
__device__ float g_att[M_ROWS * D_MODEL];

// ---------------------------------------------------------------------------
// tf32 helpers
// ---------------------------------------------------------------------------
__device__ __forceinline__ float to_tf32(float x) {
    uint32_t u;
    asm("cvt.rna.tf32.f32 %0, %1;" : "=r"(u) : "f"(x));
    return __uint_as_float(u);
}

__device__ __forceinline__ void mma_tf32(float c[4], const uint32_t a[4],
                                         const uint32_t b[2]) {
    asm volatile(
        "mma.sync.aligned.m16n8k8.row.col.f32.tf32.tf32.f32 "
        "{%0,%1,%2,%3}, {%4,%5,%6,%7}, {%8,%9}, {%0,%1,%2,%3};"
        : "+f"(c[0]), "+f"(c[1]), "+f"(c[2]), "+f"(c[3])
        : "r"(a[0]), "r"(a[1]), "r"(a[2]), "r"(a[3]),
          "r"(b[0]), "r"(b[1]));
}

// ---------------------------------------------------------------------------
// GEMM: C[M][N] = A[M][K] * W[N][K]^T (+ bias). Both operands K-contiguous
// ("TN"), which maps directly onto mma row.col with smem tiles [row][k].
// Block: 256 thr = 8 warps (2 m-rows x 4 n-cols). Warp tile 64x32.
// ---------------------------------------------------------------------------
__global__ __launch_bounds__(256) void gemm_tf32_kernel(
    const float* __restrict__ A, const float* __restrict__ W,
    const float* __restrict__ bias, float* __restrict__ C,
    int M, int N, int K)
{
    const int BM = 128, BN = 128, BK = 16;
    __shared__ float As[BM][20];   // [m][k], pad 20 -> conflict-free frag loads
    __shared__ float Bs[BN][20];   // [n][k]

    const int tid  = threadIdx.x;
    const int warp = tid >> 5;
    const int lane = tid & 31;
    const int g    = lane >> 2;    // 0..7
    const int tig  = lane & 3;     // 0..3
    const int wm   = (warp & 1) * 64;
    const int wn   = (warp >> 1) * 32;
    const int bm   = blockIdx.y * BM;
    const int bn   = blockIdx.x * BN;

    float acc[4][4][4];
#pragma unroll
    for (int mt = 0; mt < 4; mt++)
#pragma unroll
        for (int nt = 0; nt < 4; nt++)
#pragma unroll
            for (int r = 0; r < 4; r++) acc[mt][nt][r] = 0.f;

    const int lrow = tid >> 2;            // 0..63
    const int lk4  = (tid & 3) << 2;      // 0,4,8,12

    for (int k0 = 0; k0 < K; k0 += BK) {
#pragma unroll
        for (int h = 0; h < 2; h++) {
            const int r = lrow + h * 64;
            float4 a4 = *(const float4*)(A + (size_t)(bm + r) * K + k0 + lk4);
            As[r][lk4 + 0] = to_tf32(a4.x); As[r][lk4 + 1] = to_tf32(a4.y);
            As[r][lk4 + 2] = to_tf32(a4.z); As[r][lk4 + 3] = to_tf32(a4.w);
            float4 b4 = *(const float4*)(W + (size_t)(bn + r) * K + k0 + lk4);
            Bs[r][lk4 + 0] = to_tf32(b4.x); Bs[r][lk4 + 1] = to_tf32(b4.y);
            Bs[r][lk4 + 2] = to_tf32(b4.z); Bs[r][lk4 + 3] = to_tf32(b4.w);
        }
        __syncthreads();

#pragma unroll
        for (int kk = 0; kk < BK; kk += 8) {
            uint32_t af[4][4];
#pragma unroll
            for (int mt = 0; mt < 4; mt++) {
                const int m = wm + mt * 16 + g;
                af[mt][0] = __float_as_uint(As[m    ][kk + tig]);
                af[mt][1] = __float_as_uint(As[m + 8][kk + tig]);
                af[mt][2] = __float_as_uint(As[m    ][kk + tig + 4]);
                af[mt][3] = __float_as_uint(As[m + 8][kk + tig + 4]);
            }
            uint32_t bf[4][2];
#pragma unroll
            for (int nt = 0; nt < 4; nt++) {
                const int n = wn + nt * 8 + g;
                bf[nt][0] = __float_as_uint(Bs[n][kk + tig]);
                bf[nt][1] = __float_as_uint(Bs[n][kk + tig + 4]);
            }
#pragma unroll
            for (int mt = 0; mt < 4; mt++)
#pragma unroll
                for (int nt = 0; nt < 4; nt++)
                    mma_tf32(acc[mt][nt], af[mt], bf[nt]);
        }
        __syncthreads();
    }

    // epilogue: c0,c1 at (row, col..col+1), c2,c3 at (row+8, col..col+1)
#pragma unroll
    for (int mt = 0; mt < 4; mt++) {
#pragma unroll
        for (int nt = 0; nt < 4; nt++) {
            const int row = bm + wm + mt * 16 + g;
            const int col = bn + wn + nt * 8 + tig * 2;
            float b0 = 0.f, b1 = 0.f;
            if (bias) { b0 = bias[col]; b1 = bias[col + 1]; }
            float2 lo = make_float2(acc[mt][nt][0] + b0, acc[mt][nt][1] + b1);
            float2 hi = make_float2(acc[mt][nt][2] + b0, acc[mt][nt][3] + b1);
            *(float2*)(C + (size_t)row * N + col)       = lo;
            *(float2*)(C + (size_t)(row + 8) * N + col) = hi;
        }
    }
}

// ---------------------------------------------------------------------------
// Flash-attention (fp32, causal + pad mask, online softmax), float4 smem reads.
// grid: (SEQ/BQ, BATCH*N_GROUPS*HGROUP) = (8, 64); block = 128 threads.
// ---------------------------------------------------------------------------
#define BQ   128
#define BKV  64
#define QSTR 68   // float stride per row: 272B, 16B-aligned for float4

__global__ __launch_bounds__(128) void attn_kernel(const int* __restrict__ amask,
                                                   float* __restrict__ out)
{
    __shared__ float smem[BQ * QSTR];   // Q staging; reused as K(64x68)+V(64x68)
    __shared__ int   msk[BKV];

    const int t  = threadIdx.x;
    const int qb = blockIdx.x;
    const int h  = blockIdx.y;
    const int hg = h & 3;
    const int g  = (h >> 2) & 7;
    const int b  = h >> 5;
    const int sq = qb * BQ + t;

    // stage Q tile coalesced, then own row -> registers
    {
        const float* qbase = g_q + (size_t)(b * SEQ + qb * BQ) * D_MODEL
                           + g * (HGROUP * HEAD_DIM) + hg * HEAD_DIM;
#pragma unroll
        for (int i = 0; i < 16; i++) {
            int idx = t + i * 128;
            int r   = idx >> 4;
            int c4  = (idx & 15) << 2;
            *(float4*)&smem[r * QSTR + c4] =
                *(const float4*)(qbase + (size_t)r * D_MODEL + c4);
        }
    }
    __syncthreads();
    float4 qr[16];
#pragma unroll
    for (int d4 = 0; d4 < 16; d4++) qr[d4] = *(float4*)&smem[t * QSTR + d4 * 4];
    __syncthreads();

    float* Ks = smem;
    float* Vs = smem + BKV * QSTR;

    float4 accv[16];
#pragma unroll
    for (int d4 = 0; d4 < 16; d4++) accv[d4] = make_float4(0.f, 0.f, 0.f, 0.f);
    float mrun = -INFINITY;
    float lrun = 0.f;

    const int nkb = (qb * BQ + BQ - 1) / BKV + 1;
    for (int kb = 0; kb < nkb; kb++) {
        const float* kbase = g_k + (size_t)(b * SEQ + kb * BKV) * KV_DIM + g * HEAD_DIM;
        const float* vbase = g_v + (size_t)(b * SEQ + kb * BKV) * KV_DIM + g * HEAD_DIM;
#pragma unroll
        for (int i = 0; i < 8; i++) {
            int idx = t + i * 128;
            int r   = idx >> 4;
            int c4  = (idx & 15) << 2;
            *(float4*)&Ks[r * QSTR + c4] =
                *(const float4*)(kbase + (size_t)r * KV_DIM + c4);
            *(float4*)&Vs[r * QSTR + c4] =
                *(const float4*)(vbase + (size_t)r * KV_DIM + c4);
        }
        if (t < BKV) msk[t] = amask[b * SEQ + kb * BKV + t];
        __syncthreads();

        int jend = sq - kb * BKV + 1;
        if (jend > BKV) jend = BKV;
        for (int j = 0; j < jend; j++) {
            if (msk[j] == 0) continue;
            const float4* kr = (const float4*)&Ks[j * QSTR];
            float s = 0.f;
#pragma unroll
            for (int d4 = 0; d4 < 16; d4++) {
                float4 k4 = kr[d4];
                s = fmaf(qr[d4].x, k4.x, s);
                s = fmaf(qr[d4].y, k4.y, s);
                s = fmaf(qr[d4].z, k4.z, s);
                s = fmaf(qr[d4].w, k4.w, s);
            }
            s *= 0.125f;
            const float4* vr = (const float4*)&Vs[j * QSTR];
            if (s > mrun) {
                float corr = __expf(mrun - s);   // first hit: exp(-inf)=0
                lrun = lrun * corr + 1.f;
#pragma unroll
                for (int d4 = 0; d4 < 16; d4++) {
                    float4 v4 = vr[d4];
                    accv[d4].x = fmaf(accv[d4].x, corr, v4.x);
                    accv[d4].y = fmaf(accv[d4].y, corr, v4.y);
                    accv[d4].z = fmaf(accv[d4].z, corr, v4.z);
                    accv[d4].w = fmaf(accv[d4].w, corr, v4.w);
                }
                mrun = s;
            } else {
                float p = __expf(s - mrun);
                lrun += p;
#pragma unroll
                for (int d4 = 0; d4 < 16; d4++) {
                    float4 v4 = vr[d4];
                    accv[d4].x = fmaf(p, v4.x, accv[d4].x);
                    accv[d4].y = fmaf(p, v4.y, accv[d4].y);
                    accv[d4].z = fmaf(p, v4.z, accv[d4].z);
                    accv[d4].w = fmaf(p, v4.w, accv[d4].w);
                }
            }
        }
        __syncthreads();
    }

    const float inv = 1.f / lrun;
    float* obase = out + (size_t)(b * SEQ + sq) * D_MODEL
                 + g * (HGROUP * HEAD_DIM) + hg * HEAD_DIM;
#pragma unroll
    for (int d4 = 0; d4 < 16; d4++) {
        float4 o4 = make_float4(accv[d4].x * inv, accv[d4].y * inv,
                                accv[d4].z * inv, accv[d4].w * inv);
        *(float4*)(obase + d4 * 4) = o4;
    }
}

// ---------------------------------------------------------------------------
extern "C" void kernel_launch(void* const* d_in, const int* in_sizes, int n_in,
                              void* d_out, int out_size)
{
    const float* Q     = (const float*)d_in[0];
    const float* K     = (const float*)d_in[1];
    const float* V     = (const float*)d_in[2];
    const int*   amask = (const int*)  d_in[3];
    const float* w_q   = (const float*)d_in[4];
    const float* w_k   = (const float*)d_in[5];
    const float* w_v   = (const float*)d_in[6];
    const float* w_o   = (const float*)d_in[7];
    const float* b_o   = (const float*)d_in[8];
    float* out = (float*)d_out;

    float *pq, *pk, *pv, *patt;
    cudaGetSymbolAddress((void**)&pq,   g_q);
    cudaGetSymbolAddress((void**)&pk,   g_k);
    cudaGetSymbolAddress((void**)&pv,   g_v);
    cudaGetSymbolAddress((void**)&patt, g_att);

    dim3 blk(256);
    gemm_tf32_kernel<<<dim3(D_MODEL / 128, M_ROWS / 128), blk>>>(
        Q, w_q, nullptr, pq, M_ROWS, D_MODEL, D_MODEL);
    gemm_tf32_kernel<<<dim3(KV_DIM / 128, M_ROWS / 128), blk>>>(
        K, w_k, nullptr, pk, M_ROWS, KV_DIM, D_MODEL);
    gemm_tf32_kernel<<<dim3(KV_DIM / 128, M_ROWS / 128), blk>>>(
        V, w_v, nullptr, pv, M_ROWS, KV_DIM, D_MODEL);
    attn_kernel<<<dim3(SEQ / BQ, BATCH * N_GROUPS * HGROUP), dim3(128)>>>(amask, patt);
    gemm_tf32_kernel<<<dim3(D_MODEL / 128, M_ROWS / 128), blk>>>(
        patt, w_o, b_o, out, M_ROWS, D_MODEL, D_MODEL);
}

// round 3
// speedup vs baseline: 2.1079x; 1.0042x over previous
#include <cuda_runtime.h>
#include <math.h>
#include <stdint.h>

// ---------------------------------------------------------------------------
// GroupedQueryAttentionWithoutRoPE — Round 2
//   GEMMs: tf32 mma.sync.m16n8k8 (tensor cores), BM=BN=128, BK=16.
//   Attention: fp32 SIMT flash, float4 smem loads (stride 68).
// ---------------------------------------------------------------------------

#define D_MODEL   2048
#define N_GROUPS  8
#define HEAD_DIM  64
#define HGROUP    4
#define BATCH     2
#define SEQ       1024
#define M_ROWS    (BATCH * SEQ)          // 2048
#define KV_DIM    (N_GROUPS * HEAD_DIM)  // 512

__device__ float g_q  [M_ROWS * D_MODEL];
__device__ float g_k  [M_ROWS * KV_DIM];
__device__ float g_v  [M_ROWS * KV_DIM];
__device__ float g_att[M_ROWS * D_MODEL];

// ---------------------------------------------------------------------------
// tf32 helpers
// ---------------------------------------------------------------------------
__device__ __forceinline__ float to_tf32(float x) {
    uint32_t u;
    asm("cvt.rna.tf32.f32 %0, %1;" : "=r"(u) : "f"(x));
    return __uint_as_float(u);
}

__device__ __forceinline__ void mma_tf32(float c[4], const uint32_t a[4],
                                         const uint32_t b[2]) {
    asm volatile(
        "mma.sync.aligned.m16n8k8.row.col.f32.tf32.tf32.f32 "
        "{%0,%1,%2,%3}, {%4,%5,%6,%7}, {%8,%9}, {%0,%1,%2,%3};"
        : "+f"(c[0]), "+f"(c[1]), "+f"(c[2]), "+f"(c[3])
        : "r"(a[0]), "r"(a[1]), "r"(a[2]), "r"(a[3]),
          "r"(b[0]), "r"(b[1]));
}

// ---------------------------------------------------------------------------
// GEMM: C[M][N] = A[M][K] * W[N][K]^T (+ bias). Both operands K-contiguous
// ("TN"), which maps directly onto mma row.col with smem tiles [row][k].
// Block: 256 thr = 8 warps (2 m-rows x 4 n-cols). Warp tile 64x32.
// ---------------------------------------------------------------------------
__global__ __launch_bounds__(256) void gemm_tf32_kernel(
    const float* __restrict__ A, const float* __restrict__ W,
    const float* __restrict__ bias, float* __restrict__ C,
    int M, int N, int K)
{
    const int BM = 128, BN = 128, BK = 16;
    __shared__ float As[BM][20];   // [m][k], pad 20 -> conflict-free frag loads
    __shared__ float Bs[BN][20];   // [n][k]

    const int tid  = threadIdx.x;
    const int warp = tid >> 5;
    const int lane = tid & 31;
    const int g    = lane >> 2;    // 0..7
    const int tig  = lane & 3;     // 0..3
    const int wm   = (warp & 1) * 64;
    const int wn   = (warp >> 1) * 32;
    const int bm   = blockIdx.y * BM;
    const int bn   = blockIdx.x * BN;

    float acc[4][4][4];
#pragma unroll
    for (int mt = 0; mt < 4; mt++)
#pragma unroll
        for (int nt = 0; nt < 4; nt++)
#pragma unroll
            for (int r = 0; r < 4; r++) acc[mt][nt][r] = 0.f;

    const int lrow = tid >> 2;            // 0..63
    const int lk4  = (tid & 3) << 2;      // 0,4,8,12

    for (int k0 = 0; k0 < K; k0 += BK) {
#pragma unroll
        for (int h = 0; h < 2; h++) {
            const int r = lrow + h * 64;
            float4 a4 = *(const float4*)(A + (size_t)(bm + r) * K + k0 + lk4);
            As[r][lk4 + 0] = to_tf32(a4.x); As[r][lk4 + 1] = to_tf32(a4.y);
            As[r][lk4 + 2] = to_tf32(a4.z); As[r][lk4 + 3] = to_tf32(a4.w);
            float4 b4 = *(const float4*)(W + (size_t)(bn + r) * K + k0 + lk4);
            Bs[r][lk4 + 0] = to_tf32(b4.x); Bs[r][lk4 + 1] = to_tf32(b4.y);
            Bs[r][lk4 + 2] = to_tf32(b4.z); Bs[r][lk4 + 3] = to_tf32(b4.w);
        }
        __syncthreads();

#pragma unroll
        for (int kk = 0; kk < BK; kk += 8) {
            uint32_t af[4][4];
#pragma unroll
            for (int mt = 0; mt < 4; mt++) {
                const int m = wm + mt * 16 + g;
                af[mt][0] = __float_as_uint(As[m    ][kk + tig]);
                af[mt][1] = __float_as_uint(As[m + 8][kk + tig]);
                af[mt][2] = __float_as_uint(As[m    ][kk + tig + 4]);
                af[mt][3] = __float_as_uint(As[m + 8][kk + tig + 4]);
            }
            uint32_t bf[4][2];
#pragma unroll
            for (int nt = 0; nt < 4; nt++) {
                const int n = wn + nt * 8 + g;
                bf[nt][0] = __float_as_uint(Bs[n][kk + tig]);
                bf[nt][1] = __float_as_uint(Bs[n][kk + tig + 4]);
            }
#pragma unroll
            for (int mt = 0; mt < 4; mt++)
#pragma unroll
                for (int nt = 0; nt < 4; nt++)
                    mma_tf32(acc[mt][nt], af[mt], bf[nt]);
        }
        __syncthreads();
    }

    // epilogue: c0,c1 at (row, col..col+1), c2,c3 at (row+8, col..col+1)
#pragma unroll
    for (int mt = 0; mt < 4; mt++) {
#pragma unroll
        for (int nt = 0; nt < 4; nt++) {
            const int row = bm + wm + mt * 16 + g;
            const int col = bn + wn + nt * 8 + tig * 2;
            float b0 = 0.f, b1 = 0.f;
            if (bias) { b0 = bias[col]; b1 = bias[col + 1]; }
            float2 lo = make_float2(acc[mt][nt][0] + b0, acc[mt][nt][1] + b1);
            float2 hi = make_float2(acc[mt][nt][2] + b0, acc[mt][nt][3] + b1);
            *(float2*)(C + (size_t)row * N + col)       = lo;
            *(float2*)(C + (size_t)(row + 8) * N + col) = hi;
        }
    }
}

// ---------------------------------------------------------------------------
// Flash-attention (fp32, causal + pad mask, online softmax), float4 smem reads.
// grid: (SEQ/BQ, BATCH*N_GROUPS*HGROUP) = (8, 64); block = 128 threads.
// ---------------------------------------------------------------------------
#define BQ   128
#define BKV  64
#define QSTR 68   // float stride per row: 272B, 16B-aligned for float4

__global__ __launch_bounds__(128) void attn_kernel(const int* __restrict__ amask,
                                                   float* __restrict__ out)
{
    __shared__ float smem[BQ * QSTR];   // Q staging; reused as K(64x68)+V(64x68)
    __shared__ int   msk[BKV];

    const int t  = threadIdx.x;
    const int qb = blockIdx.x;
    const int h  = blockIdx.y;
    const int hg = h & 3;
    const int g  = (h >> 2) & 7;
    const int b  = h >> 5;
    const int sq = qb * BQ + t;

    // stage Q tile coalesced, then own row -> registers
    {
        const float* qbase = g_q + (size_t)(b * SEQ + qb * BQ) * D_MODEL
                           + g * (HGROUP * HEAD_DIM) + hg * HEAD_DIM;
#pragma unroll
        for (int i = 0; i < 16; i++) {
            int idx = t + i * 128;
            int r   = idx >> 4;
            int c4  = (idx & 15) << 2;
            *(float4*)&smem[r * QSTR + c4] =
                *(const float4*)(qbase + (size_t)r * D_MODEL + c4);
        }
    }
    __syncthreads();
    float4 qr[16];
#pragma unroll
    for (int d4 = 0; d4 < 16; d4++) qr[d4] = *(float4*)&smem[t * QSTR + d4 * 4];
    __syncthreads();

    float* Ks = smem;
    float* Vs = smem + BKV * QSTR;

    float4 accv[16];
#pragma unroll
    for (int d4 = 0; d4 < 16; d4++) accv[d4] = make_float4(0.f, 0.f, 0.f, 0.f);
    float mrun = -INFINITY;
    float lrun = 0.f;

    const int nkb = (qb * BQ + BQ - 1) / BKV + 1;
    for (int kb = 0; kb < nkb; kb++) {
        const float* kbase = g_k + (size_t)(b * SEQ + kb * BKV) * KV_DIM + g * HEAD_DIM;
        const float* vbase = g_v + (size_t)(b * SEQ + kb * BKV) * KV_DIM + g * HEAD_DIM;
#pragma unroll
        for (int i = 0; i < 8; i++) {
            int idx = t + i * 128;
            int r   = idx >> 4;
            int c4  = (idx & 15) << 2;
            *(float4*)&Ks[r * QSTR + c4] =
                *(const float4*)(kbase + (size_t)r * KV_DIM + c4);
            *(float4*)&Vs[r * QSTR + c4] =
                *(const float4*)(vbase + (size_t)r * KV_DIM + c4);
        }
        if (t < BKV) msk[t] = amask[b * SEQ + kb * BKV + t];
        __syncthreads();

        int jend = sq - kb * BKV + 1;
        if (jend > BKV) jend = BKV;
        for (int j = 0; j < jend; j++) {
            if (msk[j] == 0) continue;
            const float4* kr = (const float4*)&Ks[j * QSTR];
            float s = 0.f;
#pragma unroll
            for (int d4 = 0; d4 < 16; d4++) {
                float4 k4 = kr[d4];
                s = fmaf(qr[d4].x, k4.x, s);
                s = fmaf(qr[d4].y, k4.y, s);
                s = fmaf(qr[d4].z, k4.z, s);
                s = fmaf(qr[d4].w, k4.w, s);
            }
            s *= 0.125f;
            const float4* vr = (const float4*)&Vs[j * QSTR];
            if (s > mrun) {
                float corr = __expf(mrun - s);   // first hit: exp(-inf)=0
                lrun = lrun * corr + 1.f;
#pragma unroll
                for (int d4 = 0; d4 < 16; d4++) {
                    float4 v4 = vr[d4];
                    accv[d4].x = fmaf(accv[d4].x, corr, v4.x);
                    accv[d4].y = fmaf(accv[d4].y, corr, v4.y);
                    accv[d4].z = fmaf(accv[d4].z, corr, v4.z);
                    accv[d4].w = fmaf(accv[d4].w, corr, v4.w);
                }
                mrun = s;
            } else {
                float p = __expf(s - mrun);
                lrun += p;
#pragma unroll
                for (int d4 = 0; d4 < 16; d4++) {
                    float4 v4 = vr[d4];
                    accv[d4].x = fmaf(p, v4.x, accv[d4].x);
                    accv[d4].y = fmaf(p, v4.y, accv[d4].y);
                    accv[d4].z = fmaf(p, v4.z, accv[d4].z);
                    accv[d4].w = fmaf(p, v4.w, accv[d4].w);
                }
            }
        }
        __syncthreads();
    }

    const float inv = 1.f / lrun;
    float* obase = out + (size_t)(b * SEQ + sq) * D_MODEL
                 + g * (HGROUP * HEAD_DIM) + hg * HEAD_DIM;
#pragma unroll
    for (int d4 = 0; d4 < 16; d4++) {
        float4 o4 = make_float4(accv[d4].x * inv, accv[d4].y * inv,
                                accv[d4].z * inv, accv[d4].w * inv);
        *(float4*)(obase + d4 * 4) = o4;
    }
}

// ---------------------------------------------------------------------------
extern "C" void kernel_launch(void* const* d_in, const int* in_sizes, int n_in,
                              void* d_out, int out_size)
{
    const float* Q     = (const float*)d_in[0];
    const float* K     = (const float*)d_in[1];
    const float* V     = (const float*)d_in[2];
    const int*   amask = (const int*)  d_in[3];
    const float* w_q   = (const float*)d_in[4];
    const float* w_k   = (const float*)d_in[5];
    const float* w_v   = (const float*)d_in[6];
    const float* w_o   = (const float*)d_in[7];
    const float* b_o   = (const float*)d_in[8];
    float* out = (float*)d_out;

    float *pq, *pk, *pv, *patt;
    cudaGetSymbolAddress((void**)&pq,   g_q);
    cudaGetSymbolAddress((void**)&pk,   g_k);
    cudaGetSymbolAddress((void**)&pv,   g_v);
    cudaGetSymbolAddress((void**)&patt, g_att);

    dim3 blk(256);
    gemm_tf32_kernel<<<dim3(D_MODEL / 128, M_ROWS / 128), blk>>>(
        Q, w_q, nullptr, pq, M_ROWS, D_MODEL, D_MODEL);
    gemm_tf32_kernel<<<dim3(KV_DIM / 128, M_ROWS / 128), blk>>>(
        K, w_k, nullptr, pk, M_ROWS, KV_DIM, D_MODEL);
    gemm_tf32_kernel<<<dim3(KV_DIM / 128, M_ROWS / 128), blk>>>(
        V, w_v, nullptr, pv, M_ROWS, KV_DIM, D_MODEL);
    attn_kernel<<<dim3(SEQ / BQ, BATCH * N_GROUPS * HGROUP), dim3(128)>>>(amask, patt);
    gemm_tf32_kernel<<<dim3(D_MODEL / 128, M_ROWS / 128), blk>>>(
        patt, w_o, b_o, out, M_ROWS, D_MODEL, D_MODEL);
}

// round 4
// speedup vs baseline: 3.2556x; 1.5445x over previous
#include <cuda_runtime.h>
#include <math.h>
#include <stdint.h>

// ---------------------------------------------------------------------------
// GroupedQueryAttentionWithoutRoPE — Round 3
//   GEMMs: tf32 mma m16n8k8 + register-prefetch double buffering.
//   Attention: tf32 mma flash attention (Q-frags in regs, swizzled K/V smem,
//   shfl-based P C-frag -> A-frag relayout, warp-private online softmax).
// ---------------------------------------------------------------------------

#define D_MODEL   2048
#define N_GROUPS  8
#define HEAD_DIM  64
#define HGROUP    4
#define BATCH     2
#define SEQ       1024
#define M_ROWS    (BATCH * SEQ)          // 2048
#define KV_DIM    (N_GROUPS * HEAD_DIM)  // 512

__device__ float g_q  [M_ROWS * D_MODEL];
__device__ float g_k  [M_ROWS * KV_DIM];
__device__ float g_v  [M_ROWS * KV_DIM];
__device__ float g_att[M_ROWS * D_MODEL];

__device__ __forceinline__ float to_tf32(float x) {
    uint32_t u;
    asm("cvt.rna.tf32.f32 %0, %1;" : "=r"(u) : "f"(x));
    return __uint_as_float(u);
}

__device__ __forceinline__ void mma_tf32(float c[4], const uint32_t a[4],
                                         const uint32_t b[2]) {
    asm volatile(
        "mma.sync.aligned.m16n8k8.row.col.f32.tf32.tf32.f32 "
        "{%0,%1,%2,%3}, {%4,%5,%6,%7}, {%8,%9}, {%0,%1,%2,%3};"
        : "+f"(c[0]), "+f"(c[1]), "+f"(c[2]), "+f"(c[3])
        : "r"(a[0]), "r"(a[1]), "r"(a[2]), "r"(a[3]),
          "r"(b[0]), "r"(b[1]));
}

// ---------------------------------------------------------------------------
// GEMM: C[M][N] = A[M][K] * W[N][K]^T (+ bias), tf32 mma, BM=BN=128, BK=16,
// register-prefetch double buffering to hide LDG latency under compute.
// ---------------------------------------------------------------------------
__global__ __launch_bounds__(256) void gemm_tf32_kernel(
    const float* __restrict__ A, const float* __restrict__ W,
    const float* __restrict__ bias, float* __restrict__ C,
    int M, int N, int K)
{
    const int BM = 128, BN = 128, BK = 16;
    __shared__ float As[BM][20];
    __shared__ float Bs[BN][20];

    const int tid  = threadIdx.x;
    const int warp = tid >> 5;
    const int lane = tid & 31;
    const int g    = lane >> 2;
    const int tig  = lane & 3;
    const int wm   = (warp & 1) * 64;
    const int wn   = (warp >> 1) * 32;
    const int bm   = blockIdx.y * BM;
    const int bn   = blockIdx.x * BN;

    float acc[4][4][4];
#pragma unroll
    for (int mt = 0; mt < 4; mt++)
#pragma unroll
        for (int nt = 0; nt < 4; nt++)
#pragma unroll
            for (int r = 0; r < 4; r++) acc[mt][nt][r] = 0.f;

    const int lrow = tid >> 2;
    const int lk4  = (tid & 3) << 2;

    float4 pa[2], pb[2];
#pragma unroll
    for (int h = 0; h < 2; h++) {
        const int r = lrow + h * 64;
        pa[h] = *(const float4*)(A + (size_t)(bm + r) * K + lk4);
        pb[h] = *(const float4*)(W + (size_t)(bn + r) * K + lk4);
    }

    for (int k0 = 0; k0 < K; k0 += BK) {
#pragma unroll
        for (int h = 0; h < 2; h++) {
            const int r = lrow + h * 64;
            As[r][lk4 + 0] = to_tf32(pa[h].x); As[r][lk4 + 1] = to_tf32(pa[h].y);
            As[r][lk4 + 2] = to_tf32(pa[h].z); As[r][lk4 + 3] = to_tf32(pa[h].w);
            Bs[r][lk4 + 0] = to_tf32(pb[h].x); Bs[r][lk4 + 1] = to_tf32(pb[h].y);
            Bs[r][lk4 + 2] = to_tf32(pb[h].z); Bs[r][lk4 + 3] = to_tf32(pb[h].w);
        }
        __syncthreads();

        if (k0 + BK < K) {
#pragma unroll
            for (int h = 0; h < 2; h++) {
                const int r = lrow + h * 64;
                pa[h] = *(const float4*)(A + (size_t)(bm + r) * K + k0 + BK + lk4);
                pb[h] = *(const float4*)(W + (size_t)(bn + r) * K + k0 + BK + lk4);
            }
        }

#pragma unroll
        for (int kk = 0; kk < BK; kk += 8) {
            uint32_t af[4][4];
#pragma unroll
            for (int mt = 0; mt < 4; mt++) {
                const int m = wm + mt * 16 + g;
                af[mt][0] = __float_as_uint(As[m    ][kk + tig]);
                af[mt][1] = __float_as_uint(As[m + 8][kk + tig]);
                af[mt][2] = __float_as_uint(As[m    ][kk + tig + 4]);
                af[mt][3] = __float_as_uint(As[m + 8][kk + tig + 4]);
            }
            uint32_t bf[4][2];
#pragma unroll
            for (int nt = 0; nt < 4; nt++) {
                const int n = wn + nt * 8 + g;
                bf[nt][0] = __float_as_uint(Bs[n][kk + tig]);
                bf[nt][1] = __float_as_uint(Bs[n][kk + tig + 4]);
            }
#pragma unroll
            for (int mt = 0; mt < 4; mt++)
#pragma unroll
                for (int nt = 0; nt < 4; nt++)
                    mma_tf32(acc[mt][nt], af[mt], bf[nt]);
        }
        __syncthreads();
    }

#pragma unroll
    for (int mt = 0; mt < 4; mt++) {
#pragma unroll
        for (int nt = 0; nt < 4; nt++) {
            const int row = bm + wm + mt * 16 + g;
            const int col = bn + wn + nt * 8 + tig * 2;
            float b0 = 0.f, b1 = 0.f;
            if (bias) { b0 = bias[col]; b1 = bias[col + 1]; }
            float2 lo = make_float2(acc[mt][nt][0] + b0, acc[mt][nt][1] + b1);
            float2 hi = make_float2(acc[mt][nt][2] + b0, acc[mt][nt][3] + b1);
            *(float2*)(C + (size_t)row * N + col)       = lo;
            *(float2*)(C + (size_t)(row + 8) * N + col) = hi;
        }
    }
}

// ---------------------------------------------------------------------------
// MMA flash attention.
// Block: 256 thr = 8 warps, each warp owns 16 query rows (BQ=128).
// grid: (SEQ/128, BATCH*32 heads) = (8, 64).
// K tile smem: sK[kv][d ^ ((kv&7)<<3)]   (S-mma B operand)
// V tile smem: sV[d][kv ^ ((d&7)<<3)]    (PV-mma B operand, transposed)
// ---------------------------------------------------------------------------
#define AQ_STR 68

__global__ __launch_bounds__(256) void attn_mma_kernel(
    const int* __restrict__ amask, float* __restrict__ out)
{
    __shared__ float sm[128 * AQ_STR];       // Q staging; aliased as sK | sV
    __shared__ int   smsk[64];
    float* sK = sm;                          // 64*64 floats
    float* sV = sm + 4096;                   // 64*64 floats

    const int tid  = threadIdx.x;
    const int warp = tid >> 5;
    const int lane = tid & 31;
    const int g    = lane >> 2;
    const int t    = lane & 3;
    const int wm   = warp * 16;

    const int qb = blockIdx.x;
    const int h  = blockIdx.y;
    const int hg = h & 3;
    const int gi = (h >> 2) & 7;
    const int b  = h >> 5;
    const int q0 = qb * 128;
    const int row0 = q0 + wm + g;
    const int row1 = row0 + 8;

    // ---- stage Q tile coalesced, build tf32 fragments (scale 1/8 folded in)
    {
        const float* qbase = g_q + (size_t)(b * SEQ + q0) * D_MODEL
                           + gi * (HGROUP * HEAD_DIM) + hg * HEAD_DIM;
#pragma unroll
        for (int i = 0; i < 8; i++) {
            int idx = tid + i * 256;
            int r   = idx >> 4;
            int c4  = (idx & 15) << 2;
            *(float4*)&sm[r * AQ_STR + c4] =
                *(const float4*)(qbase + (size_t)r * D_MODEL + c4);
        }
    }
    __syncthreads();
    uint32_t qa[8][4];
#pragma unroll
    for (int kb = 0; kb < 8; kb++) {
        qa[kb][0] = __float_as_uint(to_tf32(0.125f * sm[(wm + g    ) * AQ_STR + kb * 8 + t    ]));
        qa[kb][1] = __float_as_uint(to_tf32(0.125f * sm[(wm + g + 8) * AQ_STR + kb * 8 + t    ]));
        qa[kb][2] = __float_as_uint(to_tf32(0.125f * sm[(wm + g    ) * AQ_STR + kb * 8 + t + 4]));
        qa[kb][3] = __float_as_uint(to_tf32(0.125f * sm[(wm + g + 8) * AQ_STR + kb * 8 + t + 4]));
    }
    __syncthreads();

    float acc[8][4];
#pragma unroll
    for (int nb = 0; nb < 8; nb++)
#pragma unroll
        for (int r = 0; r < 4; r++) acc[nb][r] = 0.f;
    float m0 = -INFINITY, m1 = -INFINITY, l0 = 0.f, l1 = 0.f;

    const float* kbase = g_k + (size_t)(b * SEQ) * KV_DIM + gi * HEAD_DIM;
    const float* vbase = g_v + (size_t)(b * SEQ) * KV_DIM + gi * HEAD_DIM;
    const int ntiles = 2 * qb + 2;

    for (int kt = 0; kt < ntiles; kt++) {
        const int kv0 = kt * 64;
        // ---- load K (swizzled) + V (transposed, swizzled) + mask
#pragma unroll
        for (int i = 0; i < 4; i++) {
            int idx = tid + i * 256;
            int r   = idx >> 4;                  // kv row 0..63
            int c4  = (idx & 15) << 2;           // d 0..60
            float4 k4 = *(const float4*)(kbase + (size_t)(kv0 + r) * KV_DIM + c4);
            float4 ks = make_float4(to_tf32(k4.x), to_tf32(k4.y),
                                    to_tf32(k4.z), to_tf32(k4.w));
            *(float4*)&sK[r * 64 + (c4 ^ ((r & 7) << 3))] = ks;
            float4 v4 = *(const float4*)(vbase + (size_t)(kv0 + r) * KV_DIM + c4);
            sV[(c4 + 0) * 64 + (r ^ (((c4 + 0) & 7) << 3))] = to_tf32(v4.x);
            sV[(c4 + 1) * 64 + (r ^ (((c4 + 1) & 7) << 3))] = to_tf32(v4.y);
            sV[(c4 + 2) * 64 + (r ^ (((c4 + 2) & 7) << 3))] = to_tf32(v4.z);
            sV[(c4 + 3) * 64 + (r ^ (((c4 + 3) & 7) << 3))] = to_tf32(v4.w);
        }
        if (tid < 64) smsk[tid] = amask[b * SEQ + kv0 + tid];
        __syncthreads();

        if (kv0 <= q0 + wm + 15) {   // warp-uniform: any of this warp's rows visible
            // ---- S = (Q/8) @ K^T
            float s[8][4];
#pragma unroll
            for (int nb = 0; nb < 8; nb++) {
#pragma unroll
                for (int r = 0; r < 4; r++) s[nb][r] = 0.f;
#pragma unroll
                for (int kb = 0; kb < 8; kb++) {
                    uint32_t bk[2];
                    const int base = (nb * 8 + g) * 64;
                    bk[0] = __float_as_uint(sK[base + ((kb * 8 + t    ) ^ (g << 3))]);
                    bk[1] = __float_as_uint(sK[base + ((kb * 8 + t + 4) ^ (g << 3))]);
                    mma_tf32(s[nb], qa[kb], bk);
                }
            }
            // ---- mask + row max
            float rm0 = -INFINITY, rm1 = -INFINITY;
#pragma unroll
            for (int nb = 0; nb < 8; nb++) {
                const int c0i = kv0 + nb * 8 + 2 * t;
                const int c1i = c0i + 1;
                const bool v0 = smsk[nb * 8 + 2 * t    ] != 0;
                const bool v1 = smsk[nb * 8 + 2 * t + 1] != 0;
                s[nb][0] = (v0 && c0i <= row0) ? s[nb][0] : -INFINITY;
                s[nb][1] = (v1 && c1i <= row0) ? s[nb][1] : -INFINITY;
                s[nb][2] = (v0 && c0i <= row1) ? s[nb][2] : -INFINITY;
                s[nb][3] = (v1 && c1i <= row1) ? s[nb][3] : -INFINITY;
                rm0 = fmaxf(rm0, fmaxf(s[nb][0], s[nb][1]));
                rm1 = fmaxf(rm1, fmaxf(s[nb][2], s[nb][3]));
            }
            rm0 = fmaxf(rm0, __shfl_xor_sync(0xffffffffu, rm0, 1));
            rm0 = fmaxf(rm0, __shfl_xor_sync(0xffffffffu, rm0, 2));
            rm1 = fmaxf(rm1, __shfl_xor_sync(0xffffffffu, rm1, 1));
            rm1 = fmaxf(rm1, __shfl_xor_sync(0xffffffffu, rm1, 2));

            const float mn0 = fmaxf(m0, rm0), mn1 = fmaxf(m1, rm1);
            const float corr0 = __expf(m0 - mn0), corr1 = __expf(m1 - mn1);
            float sum0 = 0.f, sum1 = 0.f;
#pragma unroll
            for (int nb = 0; nb < 8; nb++) {
                s[nb][0] = __expf(s[nb][0] - mn0);
                s[nb][1] = __expf(s[nb][1] - mn0);
                s[nb][2] = __expf(s[nb][2] - mn1);
                s[nb][3] = __expf(s[nb][3] - mn1);
                sum0 += s[nb][0] + s[nb][1];
                sum1 += s[nb][2] + s[nb][3];
            }
            sum0 += __shfl_xor_sync(0xffffffffu, sum0, 1);
            sum0 += __shfl_xor_sync(0xffffffffu, sum0, 2);
            sum1 += __shfl_xor_sync(0xffffffffu, sum1, 1);
            sum1 += __shfl_xor_sync(0xffffffffu, sum1, 2);
            l0 = l0 * corr0 + sum0;
            l1 = l1 * corr1 + sum1;
            m0 = mn0; m1 = mn1;
#pragma unroll
            for (int nb = 0; nb < 8; nb++) {
                acc[nb][0] *= corr0; acc[nb][1] *= corr0;
                acc[nb][2] *= corr1; acc[nb][3] *= corr1;
                s[nb][0] = to_tf32(s[nb][0]); s[nb][1] = to_tf32(s[nb][1]);
                s[nb][2] = to_tf32(s[nb][2]); s[nb][3] = to_tf32(s[nb][3]);
            }
            // ---- O += P @ V  (P C-frag -> A-frag via quad shfl)
            const int src0 = (lane & ~3) | (t >> 1);
            const int src2 = src0 + 2;
            const bool odd = (t & 1) != 0;
#pragma unroll
            for (int kb = 0; kb < 8; kb++) {
                float u0 = __shfl_sync(0xffffffffu, s[kb][0], src0);
                float u1 = __shfl_sync(0xffffffffu, s[kb][1], src0);
                float u2 = __shfl_sync(0xffffffffu, s[kb][2], src0);
                float u3 = __shfl_sync(0xffffffffu, s[kb][3], src0);
                float w0 = __shfl_sync(0xffffffffu, s[kb][0], src2);
                float w1 = __shfl_sync(0xffffffffu, s[kb][1], src2);
                float w2 = __shfl_sync(0xffffffffu, s[kb][2], src2);
                float w3 = __shfl_sync(0xffffffffu, s[kb][3], src2);
                uint32_t pa[4];
                pa[0] = __float_as_uint(odd ? u1 : u0);
                pa[1] = __float_as_uint(odd ? u3 : u2);
                pa[2] = __float_as_uint(odd ? w1 : w0);
                pa[3] = __float_as_uint(odd ? w3 : w2);
#pragma unroll
                for (int nb = 0; nb < 8; nb++) {
                    uint32_t bv[2];
                    const int base = (nb * 8 + g) * 64;
                    bv[0] = __float_as_uint(sV[base + ((kb * 8 + t    ) ^ (g << 3))]);
                    bv[1] = __float_as_uint(sV[base + ((kb * 8 + t + 4) ^ (g << 3))]);
                    mma_tf32(acc[nb], pa, bv);
                }
            }
        }
        __syncthreads();
    }

    // ---- epilogue
    const float inv0 = 1.f / l0;
    const float inv1 = 1.f / l1;
    float* ob0 = out + (size_t)(b * SEQ + row0) * D_MODEL + gi * (HGROUP * HEAD_DIM) + hg * HEAD_DIM;
    float* ob1 = out + (size_t)(b * SEQ + row1) * D_MODEL + gi * (HGROUP * HEAD_DIM) + hg * HEAD_DIM;
#pragma unroll
    for (int nb = 0; nb < 8; nb++) {
        *(float2*)(ob0 + nb * 8 + 2 * t) = make_float2(acc[nb][0] * inv0, acc[nb][1] * inv0);
        *(float2*)(ob1 + nb * 8 + 2 * t) = make_float2(acc[nb][2] * inv1, acc[nb][3] * inv1);
    }
}

// ---------------------------------------------------------------------------
extern "C" void kernel_launch(void* const* d_in, const int* in_sizes, int n_in,
                              void* d_out, int out_size)
{
    const float* Q     = (const float*)d_in[0];
    const float* K     = (const float*)d_in[1];
    const float* V     = (const float*)d_in[2];
    const int*   amask = (const int*)  d_in[3];
    const float* w_q   = (const float*)d_in[4];
    const float* w_k   = (const float*)d_in[5];
    const float* w_v   = (const float*)d_in[6];
    const float* w_o   = (const float*)d_in[7];
    const float* b_o   = (const float*)d_in[8];
    float* out = (float*)d_out;

    float *pq, *pk, *pv, *patt;
    cudaGetSymbolAddress((void**)&pq,   g_q);
    cudaGetSymbolAddress((void**)&pk,   g_k);
    cudaGetSymbolAddress((void**)&pv,   g_v);
    cudaGetSymbolAddress((void**)&patt, g_att);

    dim3 blk(256);
    gemm_tf32_kernel<<<dim3(D_MODEL / 128, M_ROWS / 128), blk>>>(
        Q, w_q, nullptr, pq, M_ROWS, D_MODEL, D_MODEL);
    gemm_tf32_kernel<<<dim3(KV_DIM / 128, M_ROWS / 128), blk>>>(
        K, w_k, nullptr, pk, M_ROWS, KV_DIM, D_MODEL);
    gemm_tf32_kernel<<<dim3(KV_DIM / 128, M_ROWS / 128), blk>>>(
        V, w_v, nullptr, pv, M_ROWS, KV_DIM, D_MODEL);
    attn_mma_kernel<<<dim3(SEQ / 128, BATCH * N_GROUPS * HGROUP), blk>>>(amask, patt);
    gemm_tf32_kernel<<<dim3(D_MODEL / 128, M_ROWS / 128), blk>>>(
        patt, w_o, b_o, out, M_ROWS, D_MODEL, D_MODEL);
}